// round 1
// baseline (speedup 1.0000x reference)
#include <cuda_runtime.h>

// Problem constants
#define TT 16384   // B*N tokens
#define DD 768
#define HH 3072
#define EE 8

// GEMM tile config
#define BM 128
#define BN 128
#define BK 8

// ---------------- scratch (device globals; no allocations allowed) ----------
__device__ int   g_cnt[EE];
__device__ int   g_tok[EE * TT];
__device__ float g_wt [EE * TT];
__device__ int   g_kidx[EE * TT];
// padded per-expert h buffer: worst case every token to one expert
__device__ float g_h[(size_t)EE * TT * HH];      // ~1.6 GB
__device__ float g_yp[(size_t)TT * 2 * DD];      // per-token, per-k partial y

// ---------------------------------------------------------------------------
__global__ void zero_cnt_kernel() {
    if (threadIdx.x < EE) g_cnt[threadIdx.x] = 0;
}

// Router: one warp per token. logits = x @ rw + rb, top-2, softmax, build lists.
__global__ __launch_bounds__(256) void router_kernel(
    const float* __restrict__ x,
    const float* __restrict__ rw,
    const float* __restrict__ rb)
{
    int gwarp = (blockIdx.x * blockDim.x + threadIdx.x) >> 5;
    int lane  = threadIdx.x & 31;
    if (gwarp >= TT) return;
    const float* xr = x + (size_t)gwarp * DD;

    float acc[EE];
#pragma unroll
    for (int e = 0; e < EE; e++) acc[e] = 0.f;

    for (int d = lane; d < DD; d += 32) {
        float xv = xr[d];
        const float4 w0 = *(const float4*)(rw + (size_t)d * EE);
        const float4 w1 = *(const float4*)(rw + (size_t)d * EE + 4);
        acc[0] += xv * w0.x; acc[1] += xv * w0.y;
        acc[2] += xv * w0.z; acc[3] += xv * w0.w;
        acc[4] += xv * w1.x; acc[5] += xv * w1.y;
        acc[6] += xv * w1.z; acc[7] += xv * w1.w;
    }
#pragma unroll
    for (int off = 16; off; off >>= 1) {
#pragma unroll
        for (int e = 0; e < EE; e++)
            acc[e] += __shfl_down_sync(0xffffffffu, acc[e], off);
    }
    if (lane == 0) {
        float lg[EE];
#pragma unroll
        for (int e = 0; e < EE; e++) lg[e] = acc[e] + rb[e];
        // top-2 (first occurrence on ties, like jax top_k)
        int i0 = 0; float v0 = lg[0];
#pragma unroll
        for (int e = 1; e < EE; e++) if (lg[e] > v0) { v0 = lg[e]; i0 = e; }
        int i1 = -1; float v1 = -3.4e38f;
#pragma unroll
        for (int e = 0; e < EE; e++) {
            if (e == i0) continue;
            if (lg[e] > v1) { v1 = lg[e]; i1 = e; }
        }
        float e1 = __expf(v1 - v0);
        float w0 = 1.f / (1.f + e1);
        float w1 = e1 * w0;

        int s0 = atomicAdd(&g_cnt[i0], 1);
        g_tok[i0 * TT + s0] = gwarp;
        g_wt [i0 * TT + s0] = w0;
        g_kidx[i0 * TT + s0] = 0;

        int s1 = atomicAdd(&g_cnt[i1], 1);
        g_tok[i1 * TT + s1] = gwarp;
        g_wt [i1 * TT + s1] = w1;
        g_kidx[i1 * TT + s1] = 1;
    }
}

__device__ __forceinline__ float gelu_exact(float v) {
    return 0.5f * v * (1.f + erff(v * 0.70710678118654752440f));
}

// GEMM1: h[slot, n] = gelu( x[tok[slot], :] @ w1[e][:, n] + b1[e][n] )
__global__ __launch_bounds__(256, 2) void gemm1_kernel(
    const float* __restrict__ x,
    const float* __restrict__ w1,
    const float* __restrict__ b1)
{
    int e   = blockIdx.z;
    int cnt = g_cnt[e];
    int m0  = blockIdx.y * BM;
    if (m0 >= cnt) return;
    int n0  = blockIdx.x * BN;
    const float* Bp = w1 + (size_t)e * DD * HH;

    __shared__ float As[BK][BM];
    __shared__ float Bs[BK][BN];

    int tid  = threadIdx.x;
    int arow = tid >> 1;
    int acol = (tid & 1) << 2;
    int brow = tid >> 5;
    int bcol = (tid & 31) << 2;
    int tx   = tid & 15, ty = tid >> 4;

    const float* aptr = nullptr;
    {
        int gr = m0 + arow;
        if (gr < cnt) aptr = x + (size_t)g_tok[e * TT + gr] * DD + acol;
    }
    const float* bptr = Bp + (size_t)brow * HH + n0 + bcol;

    float4 pa = aptr ? *(const float4*)aptr : make_float4(0.f, 0.f, 0.f, 0.f);
    float4 pb = *(const float4*)bptr;

    float acc[8][8];
#pragma unroll
    for (int i = 0; i < 8; i++)
#pragma unroll
        for (int j = 0; j < 8; j++) acc[i][j] = 0.f;

    for (int k0 = 0; k0 < DD; k0 += BK) {
        As[acol + 0][arow] = pa.x; As[acol + 1][arow] = pa.y;
        As[acol + 2][arow] = pa.z; As[acol + 3][arow] = pa.w;
        *(float4*)&Bs[brow][bcol] = pb;
        __syncthreads();
        if (k0 + BK < DD) {
            pa = aptr ? *(const float4*)(aptr + k0 + BK)
                      : make_float4(0.f, 0.f, 0.f, 0.f);
            pb = *(const float4*)(bptr + (size_t)(k0 + BK) * HH);
        }
#pragma unroll
        for (int kk = 0; kk < BK; kk++) {
            float a[8], b[8];
            *(float4*)&a[0] = *(const float4*)&As[kk][ty * 4];
            *(float4*)&a[4] = *(const float4*)&As[kk][64 + ty * 4];
            *(float4*)&b[0] = *(const float4*)&Bs[kk][tx * 4];
            *(float4*)&b[4] = *(const float4*)&Bs[kk][64 + tx * 4];
#pragma unroll
            for (int i = 0; i < 8; i++)
#pragma unroll
                for (int j = 0; j < 8; j++)
                    acc[i][j] = fmaf(a[i], b[j], acc[i][j]);
        }
        __syncthreads();
    }

    const float* b1e = b1 + e * HH + n0;
    float4 bv0 = *(const float4*)(b1e + tx * 4);
    float4 bv1 = *(const float4*)(b1e + 64 + tx * 4);
    float bb[8] = {bv0.x, bv0.y, bv0.z, bv0.w, bv1.x, bv1.y, bv1.z, bv1.w};

#pragma unroll
    for (int i = 0; i < 8; i++) {
        int r  = (i < 4) ? (ty * 4 + i) : (64 + ty * 4 + i - 4);
        int gr = m0 + r;
        if (gr >= cnt) continue;
        float* hrow = g_h + ((size_t)e * TT + gr) * HH + n0;
        float4 o0, o1;
        o0.x = gelu_exact(acc[i][0] + bb[0]);
        o0.y = gelu_exact(acc[i][1] + bb[1]);
        o0.z = gelu_exact(acc[i][2] + bb[2]);
        o0.w = gelu_exact(acc[i][3] + bb[3]);
        o1.x = gelu_exact(acc[i][4] + bb[4]);
        o1.y = gelu_exact(acc[i][5] + bb[5]);
        o1.z = gelu_exact(acc[i][6] + bb[6]);
        o1.w = gelu_exact(acc[i][7] + bb[7]);
        *(float4*)(hrow + tx * 4)      = o0;
        *(float4*)(hrow + 64 + tx * 4) = o1;
    }
}

// GEMM2: y_partial[tok, kidx, n] = ( h[slot,:] @ w2[e][:, n] + b2[e][n] ) * wt
__global__ __launch_bounds__(256, 2) void gemm2_kernel(
    const float* __restrict__ w2,
    const float* __restrict__ b2)
{
    int e   = blockIdx.z;
    int cnt = g_cnt[e];
    int m0  = blockIdx.y * BM;
    if (m0 >= cnt) return;
    int n0  = blockIdx.x * BN;
    const float* Bp = w2 + (size_t)e * HH * DD;

    __shared__ float As[BK][BM];
    __shared__ float Bs[BK][BN];

    int tid  = threadIdx.x;
    int arow = tid >> 1;
    int acol = (tid & 1) << 2;
    int brow = tid >> 5;
    int bcol = (tid & 31) << 2;
    int tx   = tid & 15, ty = tid >> 4;

    const float* aptr = nullptr;
    {
        int gr = m0 + arow;
        if (gr < cnt) aptr = g_h + ((size_t)e * TT + gr) * HH + acol;
    }
    const float* bptr = Bp + (size_t)brow * DD + n0 + bcol;

    float4 pa = aptr ? *(const float4*)aptr : make_float4(0.f, 0.f, 0.f, 0.f);
    float4 pb = *(const float4*)bptr;

    float acc[8][8];
#pragma unroll
    for (int i = 0; i < 8; i++)
#pragma unroll
        for (int j = 0; j < 8; j++) acc[i][j] = 0.f;

    for (int k0 = 0; k0 < HH; k0 += BK) {
        As[acol + 0][arow] = pa.x; As[acol + 1][arow] = pa.y;
        As[acol + 2][arow] = pa.z; As[acol + 3][arow] = pa.w;
        *(float4*)&Bs[brow][bcol] = pb;
        __syncthreads();
        if (k0 + BK < HH) {
            pa = aptr ? *(const float4*)(aptr + k0 + BK)
                      : make_float4(0.f, 0.f, 0.f, 0.f);
            pb = *(const float4*)(bptr + (size_t)(k0 + BK) * DD);
        }
#pragma unroll
        for (int kk = 0; kk < BK; kk++) {
            float a[8], b[8];
            *(float4*)&a[0] = *(const float4*)&As[kk][ty * 4];
            *(float4*)&a[4] = *(const float4*)&As[kk][64 + ty * 4];
            *(float4*)&b[0] = *(const float4*)&Bs[kk][tx * 4];
            *(float4*)&b[4] = *(const float4*)&Bs[kk][64 + tx * 4];
#pragma unroll
            for (int i = 0; i < 8; i++)
#pragma unroll
                for (int j = 0; j < 8; j++)
                    acc[i][j] = fmaf(a[i], b[j], acc[i][j]);
        }
        __syncthreads();
    }

    const float* b2e = b2 + e * DD + n0;
    float4 bv0 = *(const float4*)(b2e + tx * 4);
    float4 bv1 = *(const float4*)(b2e + 64 + tx * 4);
    float bb[8] = {bv0.x, bv0.y, bv0.z, bv0.w, bv1.x, bv1.y, bv1.z, bv1.w};

#pragma unroll
    for (int i = 0; i < 8; i++) {
        int r  = (i < 4) ? (ty * 4 + i) : (64 + ty * 4 + i - 4);
        int gr = m0 + r;
        if (gr >= cnt) continue;
        int   tok = g_tok[e * TT + gr];
        float wt  = g_wt [e * TT + gr];
        int   kx  = g_kidx[e * TT + gr];
        float* orow = g_yp + ((size_t)tok * 2 + kx) * DD + n0;
        float4 o0, o1;
        o0.x = (acc[i][0] + bb[0]) * wt;
        o0.y = (acc[i][1] + bb[1]) * wt;
        o0.z = (acc[i][2] + bb[2]) * wt;
        o0.w = (acc[i][3] + bb[3]) * wt;
        o1.x = (acc[i][4] + bb[4]) * wt;
        o1.y = (acc[i][5] + bb[5]) * wt;
        o1.z = (acc[i][6] + bb[6]) * wt;
        o1.w = (acc[i][7] + bb[7]) * wt;
        *(float4*)(orow + tx * 4)      = o0;
        *(float4*)(orow + 64 + tx * 4) = o1;
    }
}

// Residual + LayerNorm. One block (256 threads) per token; 3 elems/thread.
__device__ __forceinline__ float block_sum256(float v) {
    __shared__ float sh[8];
    int lane = threadIdx.x & 31, w = threadIdx.x >> 5;
#pragma unroll
    for (int o = 16; o; o >>= 1) v += __shfl_down_sync(0xffffffffu, v, o);
    if (lane == 0) sh[w] = v;
    __syncthreads();
    if (threadIdx.x == 0) {
        float s = 0.f;
#pragma unroll
        for (int i = 0; i < 8; i++) s += sh[i];
        sh[0] = s;
    }
    __syncthreads();
    float r = sh[0];
    __syncthreads();
    return r;
}

__global__ __launch_bounds__(256) void ln_kernel(
    const float* __restrict__ x,
    const float* __restrict__ gamma,
    const float* __restrict__ beta,
    float* __restrict__ out)
{
    int t = blockIdx.x;
    const float* xr = x   + (size_t)t * DD;
    const float* p0 = g_yp + (size_t)t * 2 * DD;
    const float* p1 = p0 + DD;

    float v[3];
    float s = 0.f;
#pragma unroll
    for (int i = 0; i < 3; i++) {
        int d = threadIdx.x + i * 256;
        v[i] = xr[d] + p0[d] + p1[d];
        s += v[i];
    }
    s = block_sum256(s);
    float mu = s * (1.f / (float)DD);
    float q = 0.f;
#pragma unroll
    for (int i = 0; i < 3; i++) { float dl = v[i] - mu; q += dl * dl; }
    q = block_sum256(q);
    float rstd = rsqrtf(q * (1.f / (float)DD) + 1e-5f);
#pragma unroll
    for (int i = 0; i < 3; i++) {
        int d = threadIdx.x + i * 256;
        out[(size_t)t * DD + d] = (v[i] - mu) * rstd * gamma[d] + beta[d];
    }
}

// ---------------------------------------------------------------------------
extern "C" void kernel_launch(void* const* d_in, const int* in_sizes, int n_in,
                              void* d_out, int out_size)
{
    (void)in_sizes; (void)n_in; (void)out_size;
    const float* x    = (const float*)d_in[0];
    const float* rw   = (const float*)d_in[1];
    const float* rb   = (const float*)d_in[2];
    const float* w1   = (const float*)d_in[3];
    const float* b1   = (const float*)d_in[4];
    const float* w2   = (const float*)d_in[5];
    const float* b2   = (const float*)d_in[6];
    const float* gam  = (const float*)d_in[7];
    const float* bet  = (const float*)d_in[8];
    float* out = (float*)d_out;

    zero_cnt_kernel<<<1, 32>>>();
    router_kernel<<<TT / 8, 256>>>(x, rw, rb);                    // 8 warps/block
    gemm1_kernel<<<dim3(HH / BN, TT / BM, EE), 256>>>(x, w1, b1);
    gemm2_kernel<<<dim3(DD / BN, TT / BM, EE), 256>>>(w2, b2);
    ln_kernel<<<TT, 256>>>(x, gam, bet, out);
}